// round 3
// baseline (speedup 1.0000x reference)
#include <cuda_runtime.h>
#include <math.h>

// Problem constants
#define BATCH 256
#define SEQ   200
#define D     64
#define MSLOT 50
#define NUMQ  1000
#define BN    (BATCH*SEQ)        // 51200 rows
#define RPC   64                 // rows per CTA in k1/k3
#define NC1   (BN/RPC)           // 800 CTAs

typedef unsigned long long ull;

// Scratch (device globals; runtime allocation is forbidden)
__device__ float g_w[BN*64];     // softmax weights, padded 50->64 (pad zeroed)
__device__ float g_e[BN*64];     // erase gate
__device__ float g_a[BN*64];     // add vector
__device__ float g_k[BN*64];     // gathered k embedding
__device__ float g_read[BN*64];  // read vectors from the scan

__device__ __forceinline__ float fsig(float x)  { return 1.f / (1.f + __expf(-x)); }
__device__ __forceinline__ float ftanh_(float x){ return 1.f - 2.f / (__expf(2.f*x) + 1.f); }

// packed f32x2 fma: d += a*b (elementwise on 2 packed floats)
__device__ __forceinline__ void ffma2(ull& d, ull a, ull b) {
    asm("fma.rn.f32x2 %0, %1, %2, %0;" : "+l"(d) : "l"(a), "l"(b));
}
__device__ __forceinline__ float2 unpack2(ull v) {
    float2 r;
    asm("mov.b64 {%0, %1}, %2;" : "=f"(r.x), "=f"(r.y) : "l"(v));
    return r;
}

// ---------------------------------------------------------------------------
// Kernel 1: gathers + fused e/a heads + w softmax. 64 rows per CTA (800 CTAs).
// Activations staged DUPLICATED+TRANSPOSED in smem: vT[c][2i]=vT[c][2i+1]=x_i
// so the gemm loop is LDS.128 -> FFMA2 with zero packing MOVs.
//   per c-iter (fused e+a): 4x LDS.128 + 16 FFMA2  (was 4 LDS + 128 FFMA ops)
// smem: vT 64x136 + W1 64x68 + W2 64x68 = 69632 B.
// ---------------------------------------------------------------------------
__global__ __launch_bounds__(256, 2)
void k1_heads(const int* __restrict__ q, const int* __restrict__ r,
              const float* __restrict__ k_emb, const float* __restrict__ v_emb,
              const float* __restrict__ Mk,
              const float* __restrict__ eW, const float* __restrict__ eb,
              const float* __restrict__ aW, const float* __restrict__ ab)
{
    extern __shared__ float sm[];
    float* vT = sm;                 // 64 x 136 (rows duplicated)
    float* W1 = sm + 64*136;        // 64 x 68
    float* W2 = W1 + 64*68;         // 64 x 68
    __shared__ int qI[RPC], xI[RPC];

    const int tid = threadIdx.x;
    const int r0  = blockIdx.x * RPC;

    if (tid < RPC) {
        int qq = q[r0+tid], rr = r[r0+tid];
        qI[tid] = qq;
        xI[tid] = qq + NUMQ*rr;
    }
    __syncthreads();

    // gather v (duplicated transpose) + stage eW^T/aW^T
    {
        const float4* v4 = reinterpret_cast<const float4*>(v_emb);
        for (int idx = tid; idx < 1024; idx += 256) {
            int i = idx & 63, c4 = idx >> 6;
            float4 v = v4[(size_t)xI[i]*16 + c4];
            int cb = c4*4;
            *reinterpret_cast<float2*>(&vT[(cb+0)*136 + 2*i]) = make_float2(v.x, v.x);
            *reinterpret_cast<float2*>(&vT[(cb+1)*136 + 2*i]) = make_float2(v.y, v.y);
            *reinterpret_cast<float2*>(&vT[(cb+2)*136 + 2*i]) = make_float2(v.z, v.z);
            *reinterpret_cast<float2*>(&vT[(cb+3)*136 + 2*i]) = make_float2(v.w, v.w);
        }
        for (int idx = tid; idx < 4096; idx += 256) {
            int c = idx & 63, j = idx >> 6;   // idx = j*64+c
            W1[c*68+j] = eW[idx];
            W2[c*68+j] = aW[idx];
        }
    }
    __syncthreads();

    const int tx = tid & 15, ty = tid >> 4;
    const int i0 = ty*4, j0 = tx*4;

    // fused e + a gemm: acc[row u][colpair p], f32x2 over (j0+2p, j0+2p+1)
    ull aE[4][2] = {}, aA[4][2] = {};
#pragma unroll 8
    for (int c = 0; c < 64; c++) {
        ulonglong2 x01 = *reinterpret_cast<ulonglong2*>(&vT[c*136 + 2*i0]);
        ulonglong2 x23 = *reinterpret_cast<ulonglong2*>(&vT[c*136 + 2*i0 + 4]);
        ulonglong2 we  = *reinterpret_cast<ulonglong2*>(&W1[c*68 + j0]);
        ulonglong2 wa  = *reinterpret_cast<ulonglong2*>(&W2[c*68 + j0]);
        ull xs[4] = {x01.x, x01.y, x23.x, x23.y};
#pragma unroll
        for (int u = 0; u < 4; u++) {
            ffma2(aE[u][0], xs[u], we.x); ffma2(aE[u][1], xs[u], we.y);
            ffma2(aA[u][0], xs[u], wa.x); ffma2(aA[u][1], xs[u], wa.y);
        }
    }
    {
        float4 be = *reinterpret_cast<const float4*>(&eb[j0]);
        float4 ba = *reinterpret_cast<const float4*>(&ab[j0]);
        float4* gE4 = reinterpret_cast<float4*>(g_e);
        float4* gA4 = reinterpret_cast<float4*>(g_a);
#pragma unroll
        for (int u = 0; u < 4; u++) {
            float2 e0 = unpack2(aE[u][0]), e1 = unpack2(aE[u][1]);
            float2 a0 = unpack2(aA[u][0]), a1 = unpack2(aA[u][1]);
            float4 oe, oa;
            oe.x = fsig(e0.x + be.x); oe.y = fsig(e0.y + be.y);
            oe.z = fsig(e1.x + be.z); oe.w = fsig(e1.y + be.w);
            oa.x = ftanh_(a0.x + ba.x); oa.y = ftanh_(a0.y + ba.y);
            oa.z = ftanh_(a1.x + ba.z); oa.w = ftanh_(a1.y + ba.w);
            gE4[(size_t)(r0 + i0 + u)*16 + tx] = oe;
            gA4[(size_t)(r0 + i0 + u)*16 + tx] = oa;
        }
    }
    __syncthreads();

    // phase 2: gather k (duplicated) + store g_k + stage Mk^T (padded)
    {
        const float4* k4 = reinterpret_cast<const float4*>(k_emb);
        float4* gK4 = reinterpret_cast<float4*>(g_k);
        for (int idx = tid; idx < 1024; idx += 256) {
            int i = idx & 63, c4 = idx >> 6;
            float4 kv = k4[(size_t)qI[i]*16 + c4];
            gK4[(size_t)(r0+i)*16 + c4] = kv;
            int cb = c4*4;
            *reinterpret_cast<float2*>(&vT[(cb+0)*136 + 2*i]) = make_float2(kv.x, kv.x);
            *reinterpret_cast<float2*>(&vT[(cb+1)*136 + 2*i]) = make_float2(kv.y, kv.y);
            *reinterpret_cast<float2*>(&vT[(cb+2)*136 + 2*i]) = make_float2(kv.z, kv.z);
            *reinterpret_cast<float2*>(&vT[(cb+3)*136 + 2*i]) = make_float2(kv.w, kv.w);
        }
        for (int idx = tid; idx < 4096; idx += 256) {
            int c = idx & 63, j = idx >> 6;
            W1[c*68+j] = (j < MSLOT) ? Mk[j*64 + c] : 0.f;
        }
    }
    __syncthreads();

    // logits gemm
    ull aL[4][2] = {};
#pragma unroll 8
    for (int c = 0; c < 64; c++) {
        ulonglong2 x01 = *reinterpret_cast<ulonglong2*>(&vT[c*136 + 2*i0]);
        ulonglong2 x23 = *reinterpret_cast<ulonglong2*>(&vT[c*136 + 2*i0 + 4]);
        ulonglong2 wm  = *reinterpret_cast<ulonglong2*>(&W1[c*68 + j0]);
        ull xs[4] = {x01.x, x01.y, x23.x, x23.y};
#pragma unroll
        for (int u = 0; u < 4; u++) {
            ffma2(aL[u][0], xs[u], wm.x); ffma2(aL[u][1], xs[u], wm.y);
        }
    }
    __syncthreads();   // done reading vT; reuse as logits buffer (pitch 66)

    float* lg = vT;
#pragma unroll
    for (int u = 0; u < 4; u++) {
        float2 l0 = unpack2(aL[u][0]), l1 = unpack2(aL[u][1]);
        int base = (i0+u)*66 + j0;
        lg[base+0] = l0.x; lg[base+1] = l0.y;
        lg[base+2] = l1.x; lg[base+3] = l1.y;
    }
    __syncthreads();

    // softmax over m<50 per row; zero the pad
    if (tid < RPC) {
        float mx = -1e30f;
        for (int j = 0; j < MSLOT; j++) mx = fmaxf(mx, lg[tid*66 + j]);
        float s = 0.f;
        for (int j = 0; j < MSLOT; j++) {
            float ev = __expf(lg[tid*66 + j] - mx);
            lg[tid*66 + j] = ev;
            s += ev;
        }
        float inv = 1.f / s;
        for (int j = 0; j < MSLOT; j++) lg[tid*66 + j] *= inv;
        for (int j = MSLOT; j < 64; j++) lg[tid*66 + j] = 0.f;
    }
    __syncthreads();

    for (int idx = tid; idx < 4096; idx += 256) {
        int c = idx & 63, i = idx >> 6;
        g_w[(size_t)(r0 + i)*64 + c] = lg[i*66 + c];
    }
}

// ---------------------------------------------------------------------------
// Kernel 2: per-batch scan with REGISTER-RESIDENT Mv (unchanged from R2).
// ---------------------------------------------------------------------------
__global__ __launch_bounds__(256)
void k2_scan(const float* __restrict__ Mv0, float* __restrict__ out)
{
    __shared__ __align__(16) float buf[2][192];    // [w(64) | e(64) | a(64)]
    __shared__ __align__(16) float pr[2][1024];    // 16 groups x 64 cols

    const int tid = threadIdx.x;
    const int b   = blockIdx.x;
    const int row0 = b * SEQ;
    const int c4 = tid & 15;
    const int g  = tid >> 4;
    const int ns = (g < 2) ? 4 : 3;                // 16*3+g<50 only for g<2

    float4 mv[4];
    const float4* m04 = reinterpret_cast<const float4*>(Mv0);
    float4* outMv = reinterpret_cast<float4*>(out) + (BN/4)
                  + (size_t)b * (SEQ+1) * 800;

    // init state + emit slot 0
#pragma unroll
    for (int jj = 0; jj < 4; jj++) if (jj < ns) {
        int m = jj*16 + g;
        float4 v = m04[m*16 + c4];
        mv[jj] = v;
        outMv[m*16 + c4] = v;
    }
    if (tid < 192) {
        size_t row = (size_t)row0 * 64;
        float v = (tid < 64)  ? g_w[row + tid]
                : (tid < 128) ? g_e[row + tid - 64]
                              : g_a[row + tid - 128];
        buf[0][tid] = v;
    }
    __syncthreads();

    for (int t = 0; t < SEQ; t++) {
        const int ph = t & 1;
        const float* bw = buf[ph];

        // prefetch next step
        float pf = 0.f;
        if (tid < 192 && (t+1) < SEQ) {
            size_t row = (size_t)(row0 + t + 1) * 64;
            const float* src = (tid < 64)  ? g_w + row + tid
                             : (tid < 128) ? g_e + row + tid - 64
                                           : g_a + row + tid - 128;
            pf = __ldg(src);
        }

        float4 e4 = *reinterpret_cast<const float4*>(&bw[64  + c4*4]);
        float4 a4 = *reinterpret_cast<const float4*>(&bw[128 + c4*4]);

        // partial read (pre-update)
        float wv[4];
        float4 s = make_float4(0,0,0,0);
#pragma unroll
        for (int jj = 0; jj < 4; jj++) if (jj < ns) {
            float w = bw[jj*16 + g];
            wv[jj] = w;
            s.x = fmaf(w, mv[jj].x, s.x);
            s.y = fmaf(w, mv[jj].y, s.y);
            s.z = fmaf(w, mv[jj].z, s.z);
            s.w = fmaf(w, mv[jj].w, s.w);
        }
        *reinterpret_cast<float4*>(&pr[ph][g*64 + c4*4]) = s;

        // update in registers + streaming store
        float4* os = outMv + (size_t)(t+1) * 800;
#pragma unroll
        for (int jj = 0; jj < 4; jj++) if (jj < ns) {
            float w = wv[jj];
            float4 m = mv[jj];
            m.x = fmaf(w, a4.x, fmaf(-m.x, w*e4.x, m.x));
            m.y = fmaf(w, a4.y, fmaf(-m.y, w*e4.y, m.y));
            m.z = fmaf(w, a4.z, fmaf(-m.z, w*e4.z, m.z));
            m.w = fmaf(w, a4.w, fmaf(-m.w, w*e4.w, m.w));
            mv[jj] = m;
            __stcs(&os[(jj*16 + g)*16 + c4], m);
        }
        if (tid < 192 && (t+1) < SEQ) buf[1-ph][tid] = pf;
        __syncthreads();

        // reduce partials -> read vector
        if (tid < 64) {
            float rd = 0.f;
#pragma unroll
            for (int gg = 0; gg < 16; gg++) rd += pr[ph][gg*64 + tid];
            g_read[(size_t)(row0 + t)*64 + tid] = rd;
        }
    }
}

// ---------------------------------------------------------------------------
// Kernel 3: f = tanh([read,k] @ fW^T + fb), p = sigmoid(f @ pW^T + pb).
// 64 rows/CTA (800 CTAs), duplicated-transposed inputs, FFMA2 inner loop.
// smem: inT 128x136 + WtF 128x68 = 104448 B.
// ---------------------------------------------------------------------------
__global__ __launch_bounds__(256, 2)
void k3_out(const float* __restrict__ fW, const float* __restrict__ fb,
            const float* __restrict__ pW, const float* __restrict__ pb,
            float* __restrict__ out)
{
    extern __shared__ float sm[];
    float* inT = sm;             // 128 x 136 (c rows: 0-63 read, 64-127 k), dup
    float* WtF = sm + 128*136;   // 128 x 68
    __shared__ float pWs[64];

    const int tid = threadIdx.x;
    const int r0  = blockIdx.x * RPC;

    const float4* rd4 = reinterpret_cast<const float4*>(g_read);
    const float4* kg4 = reinterpret_cast<const float4*>(g_k);
    for (int idx = tid; idx < 2048; idx += 256) {
        int i  = idx & 63;
        int c4 = (idx >> 6) & 15;
        int h  = idx >> 10;
        float4 v = (h == 0) ? rd4[(size_t)(r0+i)*16 + c4]
                            : kg4[(size_t)(r0+i)*16 + c4];
        int cb = h*64 + c4*4;
        *reinterpret_cast<float2*>(&inT[(cb+0)*136 + 2*i]) = make_float2(v.x, v.x);
        *reinterpret_cast<float2*>(&inT[(cb+1)*136 + 2*i]) = make_float2(v.y, v.y);
        *reinterpret_cast<float2*>(&inT[(cb+2)*136 + 2*i]) = make_float2(v.z, v.z);
        *reinterpret_cast<float2*>(&inT[(cb+3)*136 + 2*i]) = make_float2(v.w, v.w);
    }
    for (int idx = tid; idx < 8192; idx += 256) {
        int cc = idx & 127, j = idx >> 7;   // idx = j*128+cc
        WtF[cc*68 + j] = fW[idx];
    }
    if (tid < 64) pWs[tid] = pW[tid];
    __syncthreads();

    const int tx = tid & 15, ty = tid >> 4;
    const int i0 = ty*4, j0 = tx*4;

    ull acc[4][2] = {};
#pragma unroll 8
    for (int c = 0; c < 128; c++) {
        ulonglong2 x01 = *reinterpret_cast<ulonglong2*>(&inT[c*136 + 2*i0]);
        ulonglong2 x23 = *reinterpret_cast<ulonglong2*>(&inT[c*136 + 2*i0 + 4]);
        ulonglong2 w   = *reinterpret_cast<ulonglong2*>(&WtF[c*68 + j0]);
        ull xs[4] = {x01.x, x01.y, x23.x, x23.y};
#pragma unroll
        for (int u = 0; u < 4; u++) {
            ffma2(acc[u][0], xs[u], w.x); ffma2(acc[u][1], xs[u], w.y);
        }
    }
    float4 b4 = *reinterpret_cast<const float4*>(&fb[j0]);
    __syncthreads();   // done reading inT; reuse as f storage (pitch 66)

    float* fS = inT;
#pragma unroll
    for (int u = 0; u < 4; u++) {
        float2 f0 = unpack2(acc[u][0]), f1 = unpack2(acc[u][1]);
        int base = (i0+u)*66 + j0;
        fS[base+0] = ftanh_(f0.x + b4.x);
        fS[base+1] = ftanh_(f0.y + b4.y);
        fS[base+2] = ftanh_(f1.x + b4.z);
        fS[base+3] = ftanh_(f1.y + b4.w);
    }
    __syncthreads();

    if (tid < RPC) {
        float s = pb[0];
        for (int j = 0; j < 64; j++) s = fmaf(pWs[j], fS[tid*66 + j], s);
        out[r0 + tid] = fsig(s);
    }
}

// ---------------------------------------------------------------------------
extern "C" void kernel_launch(void* const* d_in, const int* in_sizes, int n_in,
                              void* d_out, int out_size)
{
    const int*   q     = (const int*)  d_in[0];
    const int*   r     = (const int*)  d_in[1];
    const float* k_emb = (const float*)d_in[2];
    const float* v_emb = (const float*)d_in[3];
    const float* Mk    = (const float*)d_in[4];
    const float* Mv0   = (const float*)d_in[5];
    const float* eW    = (const float*)d_in[6];
    const float* eb    = (const float*)d_in[7];
    const float* aW    = (const float*)d_in[8];
    const float* ab    = (const float*)d_in[9];
    const float* fW    = (const float*)d_in[10];
    const float* fb    = (const float*)d_in[11];
    const float* pW    = (const float*)d_in[12];
    const float* pb    = (const float*)d_in[13];
    float* out = (float*)d_out;

    const int SMEM1 = (64*136 + 2*64*68) * 4;     // 69632 B
    const int SMEM3 = (128*136 + 128*68) * 4;     // 104448 B
    cudaFuncSetAttribute(k1_heads, cudaFuncAttributeMaxDynamicSharedMemorySize, SMEM1);
    cudaFuncSetAttribute(k3_out,   cudaFuncAttributeMaxDynamicSharedMemorySize, SMEM3);

    k1_heads<<<NC1, 256, SMEM1>>>(q, r, k_emb, v_emb, Mk, eW, eb, aW, ab);
    k2_scan <<<BATCH, 256>>>(Mv0, out);
    k3_out  <<<NC1, 256, SMEM3>>>(fW, fb, pW, pb, out);
}

// round 4
// speedup vs baseline: 1.0499x; 1.0499x over previous
#include <cuda_runtime.h>
#include <math.h>

// Problem constants
#define BATCH 256
#define SEQ   200
#define D     64
#define MSLOT 50
#define NUMQ  1000
#define BN    (BATCH*SEQ)        // 51200 rows
#define R1    128                // rows per CTA in k1/k3
#define NC1   (BN/R1)            // 400 CTAs

// Scratch (device globals; runtime allocation is forbidden)
__device__ float g_w[BN*64];     // softmax weights, padded 50->64 (pad zeroed)
__device__ float g_e[BN*64];     // erase gate
__device__ float g_a[BN*64];     // add vector
__device__ float g_k[BN*64];     // gathered k embedding
__device__ float g_read[BN*64];  // read vectors from the scan

__device__ __forceinline__ float fsig(float x)  { return 1.f / (1.f + __expf(-x)); }
__device__ __forceinline__ float ftanh_(float x){ return 1.f - 2.f / (__expf(2.f*x) + 1.f); }

// acc[u] += xs[u] * w  for 8 rows x 4 cols
__device__ __forceinline__ void fma8x4(const float* xs, float4 w, float4* A) {
#pragma unroll
    for (int u = 0; u < 8; u++) {
        A[u].x = fmaf(xs[u], w.x, A[u].x);
        A[u].y = fmaf(xs[u], w.y, A[u].y);
        A[u].z = fmaf(xs[u], w.z, A[u].z);
        A[u].w = fmaf(xs[u], w.w, A[u].w);
    }
}

// ---------------------------------------------------------------------------
// Kernel 1 (R2 version, measured 72us): gathers + fused e/a heads + softmax.
// ---------------------------------------------------------------------------
__global__ __launch_bounds__(256, 2)
void k1_heads(const int* __restrict__ q, const int* __restrict__ r,
              const float* __restrict__ k_emb, const float* __restrict__ v_emb,
              const float* __restrict__ Mk,
              const float* __restrict__ eW, const float* __restrict__ eb,
              const float* __restrict__ aW, const float* __restrict__ ab)
{
    extern __shared__ float sm[];
    float* vT = sm;                 // 64 x 132
    float* W1 = sm + 8448;          // 64 x 68
    float* W2 = sm + 8448 + 4352;   // 64 x 68
    __shared__ int qI[R1], xI[R1];

    const int tid = threadIdx.x;
    const int r0  = blockIdx.x * R1;

    if (tid < R1) {
        int qq = q[r0+tid], rr = r[r0+tid];
        qI[tid] = qq;
        xI[tid] = qq + NUMQ*rr;
    }
    __syncthreads();

    {
        const float4* v4 = reinterpret_cast<const float4*>(v_emb);
        for (int idx = tid; idx < 2048; idx += 256) {
            int i = idx & 127, c4 = idx >> 7;
            float4 v = v4[(size_t)xI[i]*16 + c4];
            int cb = c4*4;
            vT[(cb+0)*132+i] = v.x; vT[(cb+1)*132+i] = v.y;
            vT[(cb+2)*132+i] = v.z; vT[(cb+3)*132+i] = v.w;
        }
        for (int idx = tid; idx < 4096; idx += 256) {
            int c = idx & 63, j = idx >> 6;
            W1[c*68+j] = eW[idx];
            W2[c*68+j] = aW[idx];
        }
    }
    __syncthreads();

    const int tx = tid & 15, ty = tid >> 4;
    const int i0 = ty*8, j0 = tx*4;

    float4 aE[8], aA[8];
#pragma unroll
    for (int u = 0; u < 8; u++) { aE[u] = make_float4(0,0,0,0); aA[u] = make_float4(0,0,0,0); }
#pragma unroll 4
    for (int c = 0; c < 64; c++) {
        float4 x0 = *reinterpret_cast<float4*>(&vT[c*132 + i0]);
        float4 x1 = *reinterpret_cast<float4*>(&vT[c*132 + i0 + 4]);
        float4 we = *reinterpret_cast<float4*>(&W1[c*68 + j0]);
        float4 wa = *reinterpret_cast<float4*>(&W2[c*68 + j0]);
        float xs[8] = {x0.x,x0.y,x0.z,x0.w,x1.x,x1.y,x1.z,x1.w};
        fma8x4(xs, we, aE);
        fma8x4(xs, wa, aA);
    }
    {
        float4 be = *reinterpret_cast<const float4*>(&eb[j0]);
        float4 ba = *reinterpret_cast<const float4*>(&ab[j0]);
        float4* gE4 = reinterpret_cast<float4*>(g_e);
        float4* gA4 = reinterpret_cast<float4*>(g_a);
#pragma unroll
        for (int u = 0; u < 8; u++) {
            float4 o;
            o.x = fsig(aE[u].x + be.x); o.y = fsig(aE[u].y + be.y);
            o.z = fsig(aE[u].z + be.z); o.w = fsig(aE[u].w + be.w);
            gE4[(size_t)(r0 + i0 + u)*16 + tx] = o;
            float4 p;
            p.x = ftanh_(aA[u].x + ba.x); p.y = ftanh_(aA[u].y + ba.y);
            p.z = ftanh_(aA[u].z + ba.z); p.w = ftanh_(aA[u].w + ba.w);
            gA4[(size_t)(r0 + i0 + u)*16 + tx] = p;
        }
    }
    __syncthreads();

    {
        const float4* k4 = reinterpret_cast<const float4*>(k_emb);
        float4* gK4 = reinterpret_cast<float4*>(g_k);
        for (int idx = tid; idx < 2048; idx += 256) {
            int i = idx & 127, c4 = idx >> 7;
            float4 kv = k4[(size_t)qI[i]*16 + c4];
            gK4[(size_t)(r0+i)*16 + c4] = kv;
            int cb = c4*4;
            vT[(cb+0)*132+i] = kv.x; vT[(cb+1)*132+i] = kv.y;
            vT[(cb+2)*132+i] = kv.z; vT[(cb+3)*132+i] = kv.w;
        }
        for (int idx = tid; idx < 4096; idx += 256) {
            int c = idx & 63, j = idx >> 6;
            W1[c*68+j] = (j < MSLOT) ? Mk[j*64 + c] : 0.f;
        }
    }
    __syncthreads();

    float4 aL[8];
#pragma unroll
    for (int u = 0; u < 8; u++) aL[u] = make_float4(0,0,0,0);
#pragma unroll 4
    for (int c = 0; c < 64; c++) {
        float4 x0 = *reinterpret_cast<float4*>(&vT[c*132 + i0]);
        float4 x1 = *reinterpret_cast<float4*>(&vT[c*132 + i0 + 4]);
        float4 wm = *reinterpret_cast<float4*>(&W1[c*68 + j0]);
        float xs[8] = {x0.x,x0.y,x0.z,x0.w,x1.x,x1.y,x1.z,x1.w};
        fma8x4(xs, wm, aL);
    }
    __syncthreads();

    float* lg = vT;
#pragma unroll
    for (int u = 0; u < 8; u++) {
        int base = (i0+u)*66 + j0;
        lg[base+0] = aL[u].x; lg[base+1] = aL[u].y;
        lg[base+2] = aL[u].z; lg[base+3] = aL[u].w;
    }
    __syncthreads();

    if (tid < R1) {
        float mx = -1e30f;
        for (int j = 0; j < MSLOT; j++) mx = fmaxf(mx, lg[tid*66 + j]);
        float s = 0.f;
        for (int j = 0; j < MSLOT; j++) {
            float ev = __expf(lg[tid*66 + j] - mx);
            lg[tid*66 + j] = ev;
            s += ev;
        }
        float inv = 1.f / s;
        for (int j = 0; j < MSLOT; j++) lg[tid*66 + j] *= inv;
        for (int j = MSLOT; j < 64; j++) lg[tid*66 + j] = 0.f;
    }
    __syncthreads();

    for (int idx = tid; idx < 8192; idx += 256) {
        int c = idx & 63, i = idx >> 6;
        g_w[(size_t)(r0 + i)*64 + c] = lg[i*66 + c];
    }
}

// ---------------------------------------------------------------------------
// Kernel 2: BARRIER-FREE per-batch scan. 320 threads (10 warps), NO smem,
// no __syncthreads in the loop. Warps free-run:
//  - warps 0-7: register-resident Mv slots; per-thread prefetch of w/e/a from
//    gmem (L2-resident); update + streaming STG.128 of every Mv_t slice.
//  - warps 8-9: one column per thread, private 50-reg Mv column copy; w
//    broadcast via shfl; write g_read.
// ---------------------------------------------------------------------------
__global__ __launch_bounds__(320)
void k2_scan(const float* __restrict__ Mv0, float* __restrict__ out)
{
    const int tid = threadIdx.x;
    const int b   = blockIdx.x;
    const int row0 = b * SEQ;
    float4* outMv = reinterpret_cast<float4*>(out) + (BN/4)
                  + (size_t)b * (SEQ+1) * 800;

    if (tid < 256) {
        // ---------------- store/update path ----------------
        const int c4 = tid & 15;
        const int g  = tid >> 4;
        const int ns = (g < 2) ? 4 : 3;

        float4 mv[4];
        const float4* m04 = reinterpret_cast<const float4*>(Mv0);
#pragma unroll
        for (int jj = 0; jj < 4; jj++) if (jj < ns) {
            int m = jj*16 + g;
            float4 v = m04[m*16 + c4];
            mv[jj] = v;
            outMv[m*16 + c4] = v;
        }

        // prefetch step 0
        size_t rw = (size_t)row0 * 64;
        float cw[4];
#pragma unroll
        for (int jj = 0; jj < 4; jj++)
            cw[jj] = (jj < ns) ? __ldg(&g_w[rw + jj*16 + g]) : 0.f;
        float4 ce = *reinterpret_cast<const float4*>(&g_e[rw + c4*4]);
        float4 ca = *reinterpret_cast<const float4*>(&g_a[rw + c4*4]);

        for (int t = 0; t < SEQ; t++) {
            // prefetch t+1 (registers only; no sync)
            float pw[4] = {0,0,0,0};
            float4 pe = ce, pa = ca;
            if (t+1 < SEQ) {
                size_t nw = (size_t)(row0 + t + 1) * 64;
#pragma unroll
                for (int jj = 0; jj < 4; jj++)
                    if (jj < ns) pw[jj] = __ldg(&g_w[nw + jj*16 + g]);
                pe = *reinterpret_cast<const float4*>(&g_e[nw + c4*4]);
                pa = *reinterpret_cast<const float4*>(&g_a[nw + c4*4]);
            }

            float4* os = outMv + (size_t)(t+1) * 800;
#pragma unroll
            for (int jj = 0; jj < 4; jj++) if (jj < ns) {
                float w = cw[jj];
                float4 m = mv[jj];
                m.x = fmaf(w, ca.x, fmaf(-m.x, w*ce.x, m.x));
                m.y = fmaf(w, ca.y, fmaf(-m.y, w*ce.y, m.y));
                m.z = fmaf(w, ca.z, fmaf(-m.z, w*ce.z, m.z));
                m.w = fmaf(w, ca.w, fmaf(-m.w, w*ce.w, m.w));
                mv[jj] = m;
                __stcs(&os[(jj*16 + g)*16 + c4], m);
            }
#pragma unroll
            for (int jj = 0; jj < 4; jj++) cw[jj] = pw[jj];
            ce = pe; ca = pa;
        }
    } else {
        // ---------------- read path ----------------
        const int c    = tid - 256;     // column 0..63
        const int lane = c & 31;

        float col[MSLOT];
#pragma unroll
        for (int m = 0; m < MSLOT; m++) col[m] = __ldg(&Mv0[m*64 + c]);

        // prefetch step 0 (g_w cols 50..63 are zero-padded -> safe)
        size_t rw = (size_t)row0 * 64;
        float cwA = __ldg(&g_w[rw + lane]);
        float cwB = __ldg(&g_w[rw + 32 + lane]);
        float ce  = __ldg(&g_e[rw + c]);
        float ca  = __ldg(&g_a[rw + c]);

        for (int t = 0; t < SEQ; t++) {
            float pwA = 0.f, pwB = 0.f, pe = 0.f, pa = 0.f;
            if (t+1 < SEQ) {
                size_t nw = (size_t)(row0 + t + 1) * 64;
                pwA = __ldg(&g_w[nw + lane]);
                pwB = __ldg(&g_w[nw + 32 + lane]);
                pe  = __ldg(&g_e[nw + c]);
                pa  = __ldg(&g_a[nw + c]);
            }

            float rd = 0.f;
#pragma unroll
            for (int m = 0; m < MSLOT; m++) {
                float wm = (m < 32) ? __shfl_sync(0xffffffffu, cwA, m)
                                    : __shfl_sync(0xffffffffu, cwB, m-32);
                rd = fmaf(wm, col[m], rd);
                col[m] = fmaf(wm, ca, fmaf(-col[m], wm*ce, col[m]));
            }
            g_read[(size_t)(row0 + t)*64 + c] = rd;

            cwA = pwA; cwB = pwB; ce = pe; ca = pa;
        }
    }
}

// ---------------------------------------------------------------------------
// Kernel 3 (R2 version): f = tanh([read,k] @ fW^T + fb), p = sigmoid(f@pW^T+pb)
// ---------------------------------------------------------------------------
__global__ __launch_bounds__(256, 2)
void k3_out(const float* __restrict__ fW, const float* __restrict__ fb,
            const float* __restrict__ pW, const float* __restrict__ pb,
            float* __restrict__ out)
{
    extern __shared__ float sm[];
    float* inT = sm;            // 128 x 132
    float* WtF = sm + 16896;    // 128 x 68
    __shared__ float pWs[64];

    const int tid = threadIdx.x;
    const int r0  = blockIdx.x * R1;

    const float4* rd4 = reinterpret_cast<const float4*>(g_read);
    const float4* kg4 = reinterpret_cast<const float4*>(g_k);
    for (int idx = tid; idx < 4096; idx += 256) {
        int i  = idx & 127;
        int c4 = (idx >> 7) & 15;
        int h  = idx >> 11;
        float4 v = (h == 0) ? rd4[(size_t)(r0+i)*16 + c4]
                            : kg4[(size_t)(r0+i)*16 + c4];
        int cb = h*64 + c4*4;
        inT[(cb+0)*132+i] = v.x; inT[(cb+1)*132+i] = v.y;
        inT[(cb+2)*132+i] = v.z; inT[(cb+3)*132+i] = v.w;
    }
    for (int idx = tid; idx < 8192; idx += 256) {
        int cc = idx & 127, j = idx >> 7;
        WtF[cc*68 + j] = fW[idx];
    }
    if (tid < 64) pWs[tid] = pW[tid];
    __syncthreads();

    const int tx = tid & 15, ty = tid >> 4;
    const int i0 = ty*8, j0 = tx*4;

    float4 acc[8];
#pragma unroll
    for (int u = 0; u < 8; u++) acc[u] = make_float4(0,0,0,0);
#pragma unroll 4
    for (int c = 0; c < 128; c++) {
        float4 x0 = *reinterpret_cast<float4*>(&inT[c*132 + i0]);
        float4 x1 = *reinterpret_cast<float4*>(&inT[c*132 + i0 + 4]);
        float4 w  = *reinterpret_cast<float4*>(&WtF[c*68 + j0]);
        float xs[8] = {x0.x,x0.y,x0.z,x0.w,x1.x,x1.y,x1.z,x1.w};
        fma8x4(xs, w, acc);
    }
    float4 b4 = *reinterpret_cast<const float4*>(&fb[j0]);
    __syncthreads();

    float* fS = inT;
#pragma unroll
    for (int u = 0; u < 8; u++) {
        int base = (i0+u)*66 + j0;
        fS[base+0] = ftanh_(acc[u].x + b4.x);
        fS[base+1] = ftanh_(acc[u].y + b4.y);
        fS[base+2] = ftanh_(acc[u].z + b4.z);
        fS[base+3] = ftanh_(acc[u].w + b4.w);
    }
    __syncthreads();

    if (tid < R1) {
        float s = pb[0];
        for (int j = 0; j < 64; j++) s = fmaf(pWs[j], fS[tid*66 + j], s);
        out[r0 + tid] = fsig(s);
    }
}

// ---------------------------------------------------------------------------
extern "C" void kernel_launch(void* const* d_in, const int* in_sizes, int n_in,
                              void* d_out, int out_size)
{
    const int*   q     = (const int*)  d_in[0];
    const int*   r     = (const int*)  d_in[1];
    const float* k_emb = (const float*)d_in[2];
    const float* v_emb = (const float*)d_in[3];
    const float* Mk    = (const float*)d_in[4];
    const float* Mv0   = (const float*)d_in[5];
    const float* eW    = (const float*)d_in[6];
    const float* eb    = (const float*)d_in[7];
    const float* aW    = (const float*)d_in[8];
    const float* ab    = (const float*)d_in[9];
    const float* fW    = (const float*)d_in[10];
    const float* fb    = (const float*)d_in[11];
    const float* pW    = (const float*)d_in[12];
    const float* pb    = (const float*)d_in[13];
    float* out = (float*)d_out;

    const int SMEM1 = 17152 * 4;   // 68608 B
    const int SMEM3 = 25600 * 4;   // 102400 B
    cudaFuncSetAttribute(k1_heads, cudaFuncAttributeMaxDynamicSharedMemorySize, SMEM1);
    cudaFuncSetAttribute(k3_out,   cudaFuncAttributeMaxDynamicSharedMemorySize, SMEM3);

    k1_heads<<<NC1, 256, SMEM1>>>(q, r, k_emb, v_emb, Mk, eW, eb, aW, ab);
    k2_scan <<<BATCH, 320>>>(Mv0, out);
    k3_out  <<<NC1, 256, SMEM3>>>(fW, fb, pW, pb, out);
}

// round 5
// speedup vs baseline: 1.2065x; 1.1492x over previous
#include <cuda_runtime.h>
#include <math.h>

// Problem constants
#define BATCH 256
#define SEQ   200
#define D     64
#define MSLOT 50
#define NUMQ  1000
#define BN    (BATCH*SEQ)        // 51200 rows
#define R1    128                // rows per CTA in k1/k3
#define NC1   (BN/R1)            // 400 CTAs
#define CH    25                 // k2 chunk length (steps)
#define NCH   (SEQ/CH)           // 8 chunks

// Scratch (device globals; runtime allocation is forbidden)
__device__ float g_w[BN*64];     // softmax weights, padded 50->64 (pad zeroed)
__device__ float g_e[BN*64];     // erase gate
__device__ float g_a[BN*64];     // add vector
__device__ float g_k[BN*64];     // gathered k embedding
__device__ float g_read[BN*64];  // read vectors from the scan

__device__ __forceinline__ float fsig(float x)  { return 1.f / (1.f + __expf(-x)); }
__device__ __forceinline__ float ftanh_(float x){ return 1.f - 2.f / (__expf(2.f*x) + 1.f); }

// acc[u] += xs[u] * w  for 8 rows x 4 cols
__device__ __forceinline__ void fma8x4(const float* xs, float4 w, float4* A) {
#pragma unroll
    for (int u = 0; u < 8; u++) {
        A[u].x = fmaf(xs[u], w.x, A[u].x);
        A[u].y = fmaf(xs[u], w.y, A[u].y);
        A[u].z = fmaf(xs[u], w.z, A[u].z);
        A[u].w = fmaf(xs[u], w.w, A[u].w);
    }
}

// ---------------------------------------------------------------------------
// Kernel 1: gathers + e/a heads (separate passes, fewer regs) + softmax.
// __launch_bounds__(256,3): regs <= 85 -> 3 CTAs/SM (smem 68.6KB x3 = 206KB).
// ---------------------------------------------------------------------------
__global__ __launch_bounds__(256, 3)
void k1_heads(const int* __restrict__ q, const int* __restrict__ r,
              const float* __restrict__ k_emb, const float* __restrict__ v_emb,
              const float* __restrict__ Mk,
              const float* __restrict__ eW, const float* __restrict__ eb,
              const float* __restrict__ aW, const float* __restrict__ ab)
{
    extern __shared__ float sm[];
    float* vT = sm;                 // 64 x 132
    float* W1 = sm + 8448;          // 64 x 68
    float* W2 = sm + 8448 + 4352;   // 64 x 68
    __shared__ int qI[R1], xI[R1];

    const int tid = threadIdx.x;
    const int r0  = blockIdx.x * R1;

    if (tid < R1) {
        int qq = q[r0+tid], rr = r[r0+tid];
        qI[tid] = qq;
        xI[tid] = qq + NUMQ*rr;
    }
    __syncthreads();

    {
        const float4* v4 = reinterpret_cast<const float4*>(v_emb);
        for (int idx = tid; idx < 2048; idx += 256) {
            int i = idx & 127, c4 = idx >> 7;
            float4 v = v4[(size_t)xI[i]*16 + c4];
            int cb = c4*4;
            vT[(cb+0)*132+i] = v.x; vT[(cb+1)*132+i] = v.y;
            vT[(cb+2)*132+i] = v.z; vT[(cb+3)*132+i] = v.w;
        }
        for (int idx = tid; idx < 4096; idx += 256) {
            int c = idx & 63, j = idx >> 6;
            W1[c*68+j] = eW[idx];
            W2[c*68+j] = aW[idx];
        }
    }
    __syncthreads();

    const int tx = tid & 15, ty = tid >> 4;
    const int i0 = ty*8, j0 = tx*4;

    // ---- e pass ----
    {
        float4 acc[8];
#pragma unroll
        for (int u = 0; u < 8; u++) acc[u] = make_float4(0,0,0,0);
#pragma unroll 4
        for (int c = 0; c < 64; c++) {
            float4 x0 = *reinterpret_cast<float4*>(&vT[c*132 + i0]);
            float4 x1 = *reinterpret_cast<float4*>(&vT[c*132 + i0 + 4]);
            float4 we = *reinterpret_cast<float4*>(&W1[c*68 + j0]);
            float xs[8] = {x0.x,x0.y,x0.z,x0.w,x1.x,x1.y,x1.z,x1.w};
            fma8x4(xs, we, acc);
        }
        float4 be = *reinterpret_cast<const float4*>(&eb[j0]);
        float4* gE4 = reinterpret_cast<float4*>(g_e);
#pragma unroll
        for (int u = 0; u < 8; u++) {
            float4 o;
            o.x = fsig(acc[u].x + be.x); o.y = fsig(acc[u].y + be.y);
            o.z = fsig(acc[u].z + be.z); o.w = fsig(acc[u].w + be.w);
            gE4[(size_t)(r0 + i0 + u)*16 + tx] = o;
        }
    }

    // ---- a pass ----
    {
        float4 acc[8];
#pragma unroll
        for (int u = 0; u < 8; u++) acc[u] = make_float4(0,0,0,0);
#pragma unroll 4
        for (int c = 0; c < 64; c++) {
            float4 x0 = *reinterpret_cast<float4*>(&vT[c*132 + i0]);
            float4 x1 = *reinterpret_cast<float4*>(&vT[c*132 + i0 + 4]);
            float4 wa = *reinterpret_cast<float4*>(&W2[c*68 + j0]);
            float xs[8] = {x0.x,x0.y,x0.z,x0.w,x1.x,x1.y,x1.z,x1.w};
            fma8x4(xs, wa, acc);
        }
        float4 ba = *reinterpret_cast<const float4*>(&ab[j0]);
        float4* gA4 = reinterpret_cast<float4*>(g_a);
#pragma unroll
        for (int u = 0; u < 8; u++) {
            float4 p;
            p.x = ftanh_(acc[u].x + ba.x); p.y = ftanh_(acc[u].y + ba.y);
            p.z = ftanh_(acc[u].z + ba.z); p.w = ftanh_(acc[u].w + ba.w);
            gA4[(size_t)(r0 + i0 + u)*16 + tx] = p;
        }
    }
    __syncthreads();

    // gather k (store g_k) + stage Mk^T padded
    {
        const float4* k4 = reinterpret_cast<const float4*>(k_emb);
        float4* gK4 = reinterpret_cast<float4*>(g_k);
        for (int idx = tid; idx < 2048; idx += 256) {
            int i = idx & 127, c4 = idx >> 7;
            float4 kv = k4[(size_t)qI[i]*16 + c4];
            gK4[(size_t)(r0+i)*16 + c4] = kv;
            int cb = c4*4;
            vT[(cb+0)*132+i] = kv.x; vT[(cb+1)*132+i] = kv.y;
            vT[(cb+2)*132+i] = kv.z; vT[(cb+3)*132+i] = kv.w;
        }
        for (int idx = tid; idx < 4096; idx += 256) {
            int c = idx & 63, j = idx >> 6;
            W1[c*68+j] = (j < MSLOT) ? Mk[j*64 + c] : 0.f;
        }
    }
    __syncthreads();

    float4 aL[8];
#pragma unroll
    for (int u = 0; u < 8; u++) aL[u] = make_float4(0,0,0,0);
#pragma unroll 4
    for (int c = 0; c < 64; c++) {
        float4 x0 = *reinterpret_cast<float4*>(&vT[c*132 + i0]);
        float4 x1 = *reinterpret_cast<float4*>(&vT[c*132 + i0 + 4]);
        float4 wm = *reinterpret_cast<float4*>(&W1[c*68 + j0]);
        float xs[8] = {x0.x,x0.y,x0.z,x0.w,x1.x,x1.y,x1.z,x1.w};
        fma8x4(xs, wm, aL);
    }
    __syncthreads();

    float* lg = vT;
#pragma unroll
    for (int u = 0; u < 8; u++) {
        int base = (i0+u)*66 + j0;
        lg[base+0] = aL[u].x; lg[base+1] = aL[u].y;
        lg[base+2] = aL[u].z; lg[base+3] = aL[u].w;
    }
    __syncthreads();

    if (tid < R1) {
        float mx = -1e30f;
        for (int j = 0; j < MSLOT; j++) mx = fmaxf(mx, lg[tid*66 + j]);
        float s = 0.f;
        for (int j = 0; j < MSLOT; j++) {
            float ev = __expf(lg[tid*66 + j] - mx);
            lg[tid*66 + j] = ev;
            s += ev;
        }
        float inv = 1.f / s;
        for (int j = 0; j < MSLOT; j++) lg[tid*66 + j] *= inv;
        for (int j = MSLOT; j < 64; j++) lg[tid*66 + j] = 0.f;
    }
    __syncthreads();

    for (int idx = tid; idx < 8192; idx += 256) {
        int c = idx & 63, i = idx >> 6;
        g_w[(size_t)(r0 + i)*64 + c] = lg[i*66 + c];
    }
}

// ---------------------------------------------------------------------------
// Kernel 2: per-batch scan, smem CHUNK-STAGED w/e/a (double-buffered).
// 320 threads. Per chunk (25 steps): bulk LDG of next chunk into regs while
// scanning the current chunk from smem; STS + one __syncthreads at the end.
// Loop-body gmem traffic: STORES ONLY.
//  - threads 0-255: register-resident Mv slots, update + STG.128 stream.
//  - threads 256-319: per-column private Mv copy, compute g_read (LDS bcast).
// ---------------------------------------------------------------------------
__global__ __launch_bounds__(320)
void k2_scan(const float* __restrict__ Mv0, float* __restrict__ out)
{
    __shared__ __align__(16) float sb[2][CH*192];   // 2 x 19200 B

    const int tid = threadIdx.x;
    const int b   = blockIdx.x;
    const int row0 = b * SEQ;
    float4* outMv = reinterpret_cast<float4*>(out) + (BN/4)
                  + (size_t)b * (SEQ+1) * 800;

    const float4* gw4 = reinterpret_cast<const float4*>(g_w);
    const float4* ge4 = reinterpret_cast<const float4*>(g_e);
    const float4* ga4 = reinterpret_cast<const float4*>(g_a);

    // ---- chunk loader state (4 float4 per thread covers 1200 float4) ----
    float4 regs[4];
    int   ridx[4];
#pragma unroll
    for (int i = 0; i < 4; i++) ridx[i] = tid + i*320;

    // load chunk 0
#pragma unroll
    for (int i = 0; i < 4; i++) {
        int idx = ridx[i];
        if (idx < CH*48) {
            int st = idx / 48, part = idx % 48;
            size_t rbase = (size_t)(row0 + st) * 16;
            regs[i] = (part < 16) ? __ldg(&gw4[rbase + part])
                    : (part < 32) ? __ldg(&ge4[rbase + part - 16])
                                  : __ldg(&ga4[rbase + part - 32]);
        }
    }
#pragma unroll
    for (int i = 0; i < 4; i++) {
        int idx = ridx[i];
        if (idx < CH*48) {
            int st = idx / 48, part = idx % 48;
            *reinterpret_cast<float4*>(&sb[0][st*192 + part*4]) = regs[i];
        }
    }

    // ---- per-path init ----
    const int c4 = tid & 15;
    const int g  = tid >> 4;
    const int ns = (g < 2) ? 4 : 3;
    float4 mv[4];
    float  colv[MSLOT];
    const int cc = tid - 256;

    if (tid < 256) {
        const float4* m04 = reinterpret_cast<const float4*>(Mv0);
#pragma unroll
        for (int jj = 0; jj < 4; jj++) if (jj < ns) {
            int m = jj*16 + g;
            float4 v = m04[m*16 + c4];
            mv[jj] = v;
            outMv[m*16 + c4] = v;
        }
    } else {
#pragma unroll
        for (int m = 0; m < MSLOT; m++) colv[m] = __ldg(&Mv0[m*64 + cc]);
    }
    __syncthreads();

    for (int ch = 0; ch < NCH; ch++) {
        const int p = ch & 1;
        const float* sbp = sb[p];

        // issue next chunk's loads (fire-and-forget until STS)
        if (ch + 1 < NCH) {
#pragma unroll
            for (int i = 0; i < 4; i++) {
                int idx = ridx[i];
                if (idx < CH*48) {
                    int st = idx / 48, part = idx % 48;
                    size_t rbase = (size_t)(row0 + (ch+1)*CH + st) * 16;
                    regs[i] = (part < 16) ? __ldg(&gw4[rbase + part])
                            : (part < 32) ? __ldg(&ge4[rbase + part - 16])
                                          : __ldg(&ga4[rbase + part - 32]);
                }
            }
        }

        if (tid < 256) {
            // ------- store/update path -------
            for (int st = 0; st < CH; st++) {
                const float* bw = &sbp[st*192];
                float4 e4 = *reinterpret_cast<const float4*>(&bw[64  + c4*4]);
                float4 a4 = *reinterpret_cast<const float4*>(&bw[128 + c4*4]);
                float4* os = outMv + (size_t)(ch*CH + st + 1) * 800;
#pragma unroll
                for (int jj = 0; jj < 4; jj++) if (jj < ns) {
                    float w = bw[jj*16 + g];
                    float4 m = mv[jj];
                    m.x = fmaf(w, a4.x, fmaf(-m.x, w*e4.x, m.x));
                    m.y = fmaf(w, a4.y, fmaf(-m.y, w*e4.y, m.y));
                    m.z = fmaf(w, a4.z, fmaf(-m.z, w*e4.z, m.z));
                    m.w = fmaf(w, a4.w, fmaf(-m.w, w*e4.w, m.w));
                    mv[jj] = m;
                    __stcs(&os[(jj*16 + g)*16 + c4], m);
                }
            }
        } else {
            // ------- read path (one column per thread) -------
            for (int st = 0; st < CH; st++) {
                const float* bw = &sbp[st*192];
                float ce = bw[64 + cc];
                float ca = bw[128 + cc];
                float rd = 0.f;
#pragma unroll
                for (int m = 0; m < MSLOT; m++) {
                    float wm = bw[m];              // broadcast LDS
                    rd = fmaf(wm, colv[m], rd);
                    colv[m] = fmaf(wm, ca, fmaf(-colv[m], wm*ce, colv[m]));
                }
                g_read[(size_t)(row0 + ch*CH + st)*64 + cc] = rd;
            }
        }

        // commit next chunk into the alternate buffer
        if (ch + 1 < NCH) {
#pragma unroll
            for (int i = 0; i < 4; i++) {
                int idx = ridx[i];
                if (idx < CH*48) {
                    int st = idx / 48, part = idx % 48;
                    *reinterpret_cast<float4*>(&sb[1-p][st*192 + part*4]) = regs[i];
                }
            }
        }
        __syncthreads();
    }
}

// ---------------------------------------------------------------------------
// Kernel 3 (unchanged): f = tanh([read,k] @ fW^T + fb), p = sigmoid(f@pW^T+pb)
// ---------------------------------------------------------------------------
__global__ __launch_bounds__(256, 2)
void k3_out(const float* __restrict__ fW, const float* __restrict__ fb,
            const float* __restrict__ pW, const float* __restrict__ pb,
            float* __restrict__ out)
{
    extern __shared__ float sm[];
    float* inT = sm;            // 128 x 132
    float* WtF = sm + 16896;    // 128 x 68
    __shared__ float pWs[64];

    const int tid = threadIdx.x;
    const int r0  = blockIdx.x * R1;

    const float4* rd4 = reinterpret_cast<const float4*>(g_read);
    const float4* kg4 = reinterpret_cast<const float4*>(g_k);
    for (int idx = tid; idx < 4096; idx += 256) {
        int i  = idx & 127;
        int c4 = (idx >> 7) & 15;
        int h  = idx >> 11;
        float4 v = (h == 0) ? rd4[(size_t)(r0+i)*16 + c4]
                            : kg4[(size_t)(r0+i)*16 + c4];
        int cb = h*64 + c4*4;
        inT[(cb+0)*132+i] = v.x; inT[(cb+1)*132+i] = v.y;
        inT[(cb+2)*132+i] = v.z; inT[(cb+3)*132+i] = v.w;
    }
    for (int idx = tid; idx < 8192; idx += 256) {
        int cc = idx & 127, j = idx >> 7;
        WtF[cc*68 + j] = fW[idx];
    }
    if (tid < 64) pWs[tid] = pW[tid];
    __syncthreads();

    const int tx = tid & 15, ty = tid >> 4;
    const int i0 = ty*8, j0 = tx*4;

    float4 acc[8];
#pragma unroll
    for (int u = 0; u < 8; u++) acc[u] = make_float4(0,0,0,0);
#pragma unroll 4
    for (int c = 0; c < 128; c++) {
        float4 x0 = *reinterpret_cast<float4*>(&inT[c*132 + i0]);
        float4 x1 = *reinterpret_cast<float4*>(&inT[c*132 + i0 + 4]);
        float4 w  = *reinterpret_cast<float4*>(&WtF[c*68 + j0]);
        float xs[8] = {x0.x,x0.y,x0.z,x0.w,x1.x,x1.y,x1.z,x1.w};
        fma8x4(xs, w, acc);
    }
    float4 b4 = *reinterpret_cast<const float4*>(&fb[j0]);
    __syncthreads();

    float* fS = inT;
#pragma unroll
    for (int u = 0; u < 8; u++) {
        int base = (i0+u)*66 + j0;
        fS[base+0] = ftanh_(acc[u].x + b4.x);
        fS[base+1] = ftanh_(acc[u].y + b4.y);
        fS[base+2] = ftanh_(acc[u].z + b4.z);
        fS[base+3] = ftanh_(acc[u].w + b4.w);
    }
    __syncthreads();

    if (tid < R1) {
        float s = pb[0];
        for (int j = 0; j < 64; j++) s = fmaf(pWs[j], fS[tid*66 + j], s);
        out[r0 + tid] = fsig(s);
    }
}

// ---------------------------------------------------------------------------
extern "C" void kernel_launch(void* const* d_in, const int* in_sizes, int n_in,
                              void* d_out, int out_size)
{
    const int*   q     = (const int*)  d_in[0];
    const int*   r     = (const int*)  d_in[1];
    const float* k_emb = (const float*)d_in[2];
    const float* v_emb = (const float*)d_in[3];
    const float* Mk    = (const float*)d_in[4];
    const float* Mv0   = (const float*)d_in[5];
    const float* eW    = (const float*)d_in[6];
    const float* eb    = (const float*)d_in[7];
    const float* aW    = (const float*)d_in[8];
    const float* ab    = (const float*)d_in[9];
    const float* fW    = (const float*)d_in[10];
    const float* fb    = (const float*)d_in[11];
    const float* pW    = (const float*)d_in[12];
    const float* pb    = (const float*)d_in[13];
    float* out = (float*)d_out;

    const int SMEM1 = 17152 * 4;   // 68608 B
    const int SMEM3 = 25600 * 4;   // 102400 B
    cudaFuncSetAttribute(k1_heads, cudaFuncAttributeMaxDynamicSharedMemorySize, SMEM1);
    cudaFuncSetAttribute(k3_out,   cudaFuncAttributeMaxDynamicSharedMemorySize, SMEM3);

    k1_heads<<<NC1, 256, SMEM1>>>(q, r, k_emb, v_emb, Mk, eW, eb, aW, ab);
    k2_scan <<<BATCH, 320>>>(Mv0, out);
    k3_out  <<<NC1, 256, SMEM3>>>(fW, fb, pW, pb, out);
}